// round 9
// baseline (speedup 1.0000x reference)
#include <cuda_runtime.h>
#include <cuda_bf16.h>

// Box_diamond: two-layer soft-AND over 8-wide bins.
// out[b,p] = 1/(1 - log prod_m( (s_m - W2[p,m]) / s_m )),
// s_m = 1 - log prod_{l:|l-m|<=3} (1 - x[..]*W1[p,l-m]),  p = 4g+j
// W1[p,d]=sigmoid(d*(t2-d)) <=6e-6 for |d|>=4 -> truncated window.
// R9: R5's 2-tile/2048-block schedule + permuted SMEM (slot(l,g)=l*4+g,
// pitch 144 -> conflict-free LDS.64 snapshot) with staging iterated over
// DST slots (conflict-free STS; R8's 4-way STS conflict fixed), direct
// coalesced stores (no transpose, 2 barriers/block), W1 in regs, f32x2 math.

#define D_TOT   4096
#define P_TOT   512
#define NTH     256
#define PITCH   144          // floats; phases of 16 lanes -> all 32 banks

typedef unsigned long long u64;

#define ONE2     0x3F8000003F800000ULL  // {1.0f, 1.0f}
#define NEGLN2_2 0xBF317218BF317218ULL  // {-ln2, -ln2}

__device__ __forceinline__ u64 fma2(u64 a, u64 b, u64 c) {
    u64 d; asm("fma.rn.f32x2 %0, %1, %2, %3;" : "=l"(d) : "l"(a), "l"(b), "l"(c)); return d;
}
__device__ __forceinline__ u64 mul2(u64 a, u64 b) {
    u64 d; asm("mul.rn.f32x2 %0, %1, %2;" : "=l"(d) : "l"(a), "l"(b)); return d;
}
__device__ __forceinline__ u64 pack2(float lo, float hi) {
    u64 d; asm("mov.b64 %0, {%1, %2};" : "=l"(d) : "f"(lo), "f"(hi)); return d;
}
__device__ __forceinline__ void unpack2(float& lo, float& hi, u64 v) {
    asm("mov.b64 {%0, %1}, %2;" : "=f"(lo), "=f"(hi) : "l"(v));
}
__device__ __forceinline__ float frcp(float v) {
    float r; asm("rcp.approx.f32 %0, %1;" : "=f"(r) : "f"(v)); return r;
}
__device__ __forceinline__ float fsigmoid(float z) {
    return frcp(1.0f + __expf(-z));
}
__device__ __forceinline__ unsigned smem_u32(const void* p) {
    return (unsigned)__cvta_generic_to_shared(p);
}
__device__ __forceinline__ void cp_async16(unsigned dst, const void* src) {
    asm volatile("cp.async.cg.shared.global [%0], [%1], 16;" :: "r"(dst), "l"(src));
}
__device__ __forceinline__ void st_stream_f2(float* p, float a, float b) {
    asm volatile("st.global.cs.v2.f32 [%0], {%1, %2};" :: "l"(p), "f"(a), "f"(b));
}

__global__ __launch_bounds__(NTH, 4)
void box_diamond_kernel(const float* __restrict__ x,
                        const float* __restrict__ t0,
                        const float* __restrict__ t1,
                        const float* __restrict__ t2,
                        float* __restrict__ out) {
    __shared__ __align__(16) float xs[2][32][PITCH];  // 36.9 KB double buffer
    __shared__ float w1s[7][16];   // -W1 [d+3][p_local]
    __shared__ float w2s[8][16];   // 1-W2 [m][p_local]

    const int tid   = threadIdx.x;
    const int by    = blockIdx.y;           // p-tile of 16
    const int pbase = by * 16;
    const int b0    = blockIdx.x * 64;      // two consecutive 32-row tiles

    // staging: iterate over DST slots (contiguous STS -> conflict-free).
    // slot s holds floats of (l = s>>2, g = s&3); its GMEM chunk is
    // c = g*8 + l = (s&3)*8 + (s>>2). Warp covers one 512B row segment.
    const float* xbase = x + (size_t)by * 128;

    #pragma unroll
    for (int pre = 0; pre < 2; pre++) {
        const float* src = xbase + (size_t)(b0 + pre * 32) * D_TOT;
        #pragma unroll
        for (int it = 0; it < 4; it++) {
            int idx = it * NTH + tid;
            int r   = idx >> 5;
            int s   = idx & 31;
            int c   = (s & 3) * 8 + (s >> 2);
            cp_async16(smem_u32(&xs[pre][r][s * 4]),
                       src + (size_t)r * D_TOT + c * 4);
        }
        asm volatile("cp.async.commit_group;");
    }

    // ---- build tables (overlaps copy flight) ----
    if (tid < 112) {              // -W1: 7d x 16p
        int d  = tid >> 4;
        int pl = tid & 15;
        float dd = (float)(d - 3);
        w1s[d][pl] = -fsigmoid(dd * (t2[pbase + pl] - dd));
    }
    if (tid < 128) {              // 1-W2: 8m x 16p
        int m  = tid >> 4;
        int pl = tid & 15;
        int p  = pbase + pl;
        float lf = (float)m;
        float z1 = (lf - t0[p]) * (t1[p] - lf);
        float z2 = (7.0f - t2[p] - lf) * lf;
        w2s[m][pl] = 1.0f - fsigmoid(z1) * fsigmoid(z2);
    }

    // compute-side mapping: lane = b4*8 + sub
    const int w    = tid >> 5;
    const int lane = tid & 31;
    const int b4   = lane >> 3;             // 0..3
    const int sub  = lane & 7;              // p-pair (p_local = 2*sub)
    const int row  = w * 4 + b4;            // 0..31 within tile
    const int roff = (sub >> 1) * 4 + (sub & 1) * 2;   // g*4 + jp*2

    const float LN2 = 0.6931471805599453f;

    // ---- tile 0 ready (tile 1 still in flight) ----
    asm volatile("cp.async.wait_group 1;");
    __syncthreads();

    u64 w1r[7];
    #pragma unroll
    for (int d = 0; d < 7; d++)
        w1r[d] = *reinterpret_cast<const u64*>(&w1s[d][sub * 2]);

    #pragma unroll
    for (int t = 0; t < 2; t++) {
        // snapshot x: 8 conflict-free LDS.64
        // float offset of (l, g, jp) = l*16 + g*4 + jp*2
        u64 nx[8];
        #pragma unroll
        for (int l = 0; l < 8; l++)
            nx[l] = *reinterpret_cast<const u64*>(&xs[t][row][l * 16 + roff]);

        // compute: 8 m, truncated l-window
        u64 num = ONE2, den = ONE2;
        #pragma unroll
        for (int m = 0; m < 8; m++) {
            const int lo = (m - 3 < 0) ? 0 : m - 3;
            const int hi = (m + 3 > 7) ? 7 : m + 3;
            u64 pr = fma2(nx[lo], w1r[lo - m + 3], ONE2);   // 1 - x*W1
            #pragma unroll
            for (int l = lo + 1; l <= hi; l++)
                pr = mul2(pr, fma2(nx[l], w1r[l - m + 3], ONE2));
            float a0, a1;
            unpack2(a0, a1, pr);
            u64 lg  = pack2(__log2f(a0), __log2f(a1));
            u64 w2v = *reinterpret_cast<const u64*>(&w2s[m][sub * 2]);
            num = mul2(num, fma2(lg, NEGLN2_2, w2v));   // s - W2
            den = mul2(den, fma2(lg, NEGLN2_2, ONE2));  // s
        }

        float n0, n1, d0, d1;
        unpack2(n0, n1, num);
        unpack2(d0, d1, den);
        float o0 = frcp(fmaf(-LN2, __log2f(n0) - __log2f(d0), 1.0f));
        float o1 = frcp(fmaf(-LN2, __log2f(n1) - __log2f(d1), 1.0f));

        // direct coalesced store (64B per b-row segment)
        int brow = b0 + t * 32 + row;
        st_stream_f2(out + (size_t)brow * P_TOT + pbase + sub * 2, o0, o1);

        if (t == 0) {   // tile 1 arrival (no buffer reuse -> single barrier)
            asm volatile("cp.async.wait_group 0;");
            __syncthreads();
        }
    }
}

extern "C" void kernel_launch(void* const* d_in, const int* in_sizes, int n_in,
                              void* d_out, int out_size) {
    const float* x  = (const float*)d_in[0];
    const float* t0 = (const float*)d_in[1];
    const float* t1 = (const float*)d_in[2];
    const float* t2 = (const float*)d_in[3];
    float* out = (float*)d_out;

    int B = in_sizes[0] / D_TOT;              // 4096
    dim3 grid(B / 64, P_TOT / 16);            // (64, 32) = 2048 blocks
    box_diamond_kernel<<<grid, NTH>>>(x, t0, t1, t2, out);
}

// round 10
// speedup vs baseline: 1.0809x; 1.0809x over previous
#include <cuda_runtime.h>
#include <cuda_bf16.h>

// Box_diamond: two-layer soft-AND over 8-wide bins.
// out[b,p] = 1/(1 - log prod_m( (s_m - W2[p,m]) / s_m )),
// s_m = 1 - log prod_{l:|l-m|<=3} (1 - x[..]*W1[p,l-m]),  p = 4g+j
// W1[p,d]=sigmoid(d*(t2-d)) <=6e-6 for |d|>=4 -> truncated window.
// R10: R9 datapath (permuted conflict-free SMEM, direct coalesced stores,
// W1 in regs, f32x2 math) + L1tex queue-order fix: t0/t1/t2 LDGs issued
// BEFORE the cp.async burst so the table build never queues behind the
// tile copies (R8/R9's serialization bug).

#define D_TOT   4096
#define P_TOT   512
#define NTH     256
#define PITCH   144          // floats; phases of 16 lanes -> all 32 banks

typedef unsigned long long u64;

#define ONE2     0x3F8000003F800000ULL  // {1.0f, 1.0f}
#define NEGLN2_2 0xBF317218BF317218ULL  // {-ln2, -ln2}

__device__ __forceinline__ u64 fma2(u64 a, u64 b, u64 c) {
    u64 d; asm("fma.rn.f32x2 %0, %1, %2, %3;" : "=l"(d) : "l"(a), "l"(b), "l"(c)); return d;
}
__device__ __forceinline__ u64 mul2(u64 a, u64 b) {
    u64 d; asm("mul.rn.f32x2 %0, %1, %2;" : "=l"(d) : "l"(a), "l"(b)); return d;
}
__device__ __forceinline__ u64 pack2(float lo, float hi) {
    u64 d; asm("mov.b64 %0, {%1, %2};" : "=l"(d) : "f"(lo), "f"(hi)); return d;
}
__device__ __forceinline__ void unpack2(float& lo, float& hi, u64 v) {
    asm("mov.b64 {%0, %1}, %2;" : "=f"(lo), "=f"(hi) : "l"(v));
}
__device__ __forceinline__ float frcp(float v) {
    float r; asm("rcp.approx.f32 %0, %1;" : "=f"(r) : "f"(v)); return r;
}
__device__ __forceinline__ float fsigmoid(float z) {
    return frcp(1.0f + __expf(-z));
}
__device__ __forceinline__ unsigned smem_u32(const void* p) {
    return (unsigned)__cvta_generic_to_shared(p);
}
__device__ __forceinline__ void cp_async16(unsigned dst, const void* src) {
    asm volatile("cp.async.cg.shared.global [%0], [%1], 16;" :: "r"(dst), "l"(src));
}
__device__ __forceinline__ void st_stream_f2(float* p, float a, float b) {
    asm volatile("st.global.cs.v2.f32 [%0], {%1, %2};" :: "l"(p), "f"(a), "f"(b));
}

__global__ __launch_bounds__(NTH, 4)
void box_diamond_kernel(const float* __restrict__ x,
                        const float* __restrict__ t0,
                        const float* __restrict__ t1,
                        const float* __restrict__ t2,
                        float* __restrict__ out) {
    __shared__ __align__(16) float xs[2][32][PITCH];  // 36.9 KB double buffer
    __shared__ float w1s[7][16];   // -W1 [d+3][p_local]
    __shared__ float w2s[8][16];   // 1-W2 [m][p_local]

    const int tid   = threadIdx.x;
    const int by    = blockIdx.y;           // p-tile of 16
    const int pbase = by * 16;
    const int b0    = blockIdx.x * 64;      // two consecutive 32-row tiles

    // ---- t-parameter LDGs FIRST: they sit at the front of the L1tex FIFO,
    //      so the table build (below) never waits behind the cp.async burst.
    float rt0 = 0.f, rt1 = 0.f, rt2 = 0.f;
    const int pl_t = tid & 15;
    if (tid < 128) {
        rt0 = __ldg(t0 + pbase + pl_t);
        rt1 = __ldg(t1 + pbase + pl_t);
        rt2 = __ldg(t2 + pbase + pl_t);
    }

    // ---- stage both tiles (permuted slots; STS conflict-free) ----
    // slot s holds (l = s>>2, g = s&3); GMEM chunk c = (s&3)*8 + (s>>2).
    const float* xbase = x + (size_t)by * 128;
    #pragma unroll
    for (int pre = 0; pre < 2; pre++) {
        const float* src = xbase + (size_t)(b0 + pre * 32) * D_TOT;
        #pragma unroll
        for (int it = 0; it < 4; it++) {
            int idx = it * NTH + tid;
            int r   = idx >> 5;
            int s   = idx & 31;
            int c   = (s & 3) * 8 + (s >> 2);
            cp_async16(smem_u32(&xs[pre][r][s * 4]),
                       src + (size_t)r * D_TOT + c * 4);
        }
        asm volatile("cp.async.commit_group;");
    }

    // ---- build tables from registers (MUFU only; overlaps copy flight) ----
    if (tid < 112) {              // -W1: 7d x 16p
        int d  = tid >> 4;
        float dd = (float)(d - 3);
        w1s[d][pl_t] = -fsigmoid(dd * (rt2 - dd));
    }
    if (tid < 128) {              // 1-W2: 8m x 16p
        int m  = tid >> 4;
        float lf = (float)m;
        float z1 = (lf - rt0) * (rt1 - lf);
        float z2 = (7.0f - rt2 - lf) * lf;
        w2s[m][pl_t] = 1.0f - fsigmoid(z1) * fsigmoid(z2);
    }

    // compute-side mapping: lane = b4*8 + sub
    const int w    = tid >> 5;
    const int lane = tid & 31;
    const int b4   = lane >> 3;             // 0..3
    const int sub  = lane & 7;              // p-pair (p_local = 2*sub)
    const int row  = w * 4 + b4;            // 0..31 within tile
    const int roff = sub * 2;               // = g*4 + jp*2

    const float LN2 = 0.6931471805599453f;

    // ---- tile 0 ready (tile 1 still in flight) ----
    asm volatile("cp.async.wait_group 1;");
    __syncthreads();

    u64 w1r[7];
    #pragma unroll
    for (int d = 0; d < 7; d++)
        w1r[d] = *reinterpret_cast<const u64*>(&w1s[d][sub * 2]);

    #pragma unroll
    for (int t = 0; t < 2; t++) {
        // snapshot x: 8 conflict-free LDS.64
        // float offset of (l, g, jp) = l*16 + g*4 + jp*2
        u64 nx[8];
        #pragma unroll
        for (int l = 0; l < 8; l++)
            nx[l] = *reinterpret_cast<const u64*>(&xs[t][row][l * 16 + roff]);

        // compute: 8 m, truncated l-window
        u64 num = ONE2, den = ONE2;
        #pragma unroll
        for (int m = 0; m < 8; m++) {
            const int lo = (m - 3 < 0) ? 0 : m - 3;
            const int hi = (m + 3 > 7) ? 7 : m + 3;
            u64 pr = fma2(nx[lo], w1r[lo - m + 3], ONE2);   // 1 - x*W1
            #pragma unroll
            for (int l = lo + 1; l <= hi; l++)
                pr = mul2(pr, fma2(nx[l], w1r[l - m + 3], ONE2));
            float a0, a1;
            unpack2(a0, a1, pr);
            u64 lg  = pack2(__log2f(a0), __log2f(a1));
            u64 w2v = *reinterpret_cast<const u64*>(&w2s[m][sub * 2]);
            num = mul2(num, fma2(lg, NEGLN2_2, w2v));   // s - W2
            den = mul2(den, fma2(lg, NEGLN2_2, ONE2));  // s
        }

        float n0, n1, d0, d1;
        unpack2(n0, n1, num);
        unpack2(d0, d1, den);
        float o0 = frcp(fmaf(-LN2, __log2f(n0) - __log2f(d0), 1.0f));
        float o1 = frcp(fmaf(-LN2, __log2f(n1) - __log2f(d1), 1.0f));

        // direct coalesced store (64B per b-row segment)
        int brow = b0 + t * 32 + row;
        st_stream_f2(out + (size_t)brow * P_TOT + pbase + sub * 2, o0, o1);

        if (t == 0) {   // tile 1 arrival (distinct buffer -> single wait)
            asm volatile("cp.async.wait_group 0;");
            __syncthreads();
        }
    }
}

extern "C" void kernel_launch(void* const* d_in, const int* in_sizes, int n_in,
                              void* d_out, int out_size) {
    const float* x  = (const float*)d_in[0];
    const float* t0 = (const float*)d_in[1];
    const float* t1 = (const float*)d_in[2];
    const float* t2 = (const float*)d_in[3];
    float* out = (float*)d_out;

    int B = in_sizes[0] / D_TOT;              // 4096
    dim3 grid(B / 64, P_TOT / 16);            // (64, 32) = 2048 blocks
    box_diamond_kernel<<<grid, NTH>>>(x, t0, t1, t2, out);
}

// round 11
// speedup vs baseline: 1.1892x; 1.1001x over previous
#include <cuda_runtime.h>
#include <cuda_bf16.h>

// Box_diamond: two-layer soft-AND over 8-wide bins.
// out[b,p] = 1/(1 - log prod_m( (s_m - W2[p,m]) / s_m )),
// s_m = 1 - log prod_{l:|l-m|<=3} (1 - x[..]*W1[p,l-m]),  p = 4g+j
// W1[p,d]=sigmoid(d*(t2-d)) <=6e-6 for |d|>=4 -> truncated window.
// R11: permutation moved into the register path. LDG.128 of permuted gmem
// chunks (coalescer merges the contiguous set) -> STS.128 linear slots
// (conflict-free) -> pitch-144 layout gives conflict-free LDS.64 snapshot.
// ONE block barrier; direct coalesced stores; W1 in regs; f32x2 math.

#define D_TOT   4096
#define P_TOT   512
#define NTH     256
#define PITCH   144          // floats; snapshot phases cover all 32 banks

typedef unsigned long long u64;

#define ONE2     0x3F8000003F800000ULL  // {1.0f, 1.0f}
#define NEGLN2_2 0xBF317218BF317218ULL  // {-ln2, -ln2}

__device__ __forceinline__ u64 fma2(u64 a, u64 b, u64 c) {
    u64 d; asm("fma.rn.f32x2 %0, %1, %2, %3;" : "=l"(d) : "l"(a), "l"(b), "l"(c)); return d;
}
__device__ __forceinline__ u64 mul2(u64 a, u64 b) {
    u64 d; asm("mul.rn.f32x2 %0, %1, %2;" : "=l"(d) : "l"(a), "l"(b)); return d;
}
__device__ __forceinline__ u64 pack2(float lo, float hi) {
    u64 d; asm("mov.b64 %0, {%1, %2};" : "=l"(d) : "f"(lo), "f"(hi)); return d;
}
__device__ __forceinline__ void unpack2(float& lo, float& hi, u64 v) {
    asm("mov.b64 {%0, %1}, %2;" : "=f"(lo), "=f"(hi) : "l"(v));
}
__device__ __forceinline__ float frcp(float v) {
    float r; asm("rcp.approx.f32 %0, %1;" : "=f"(r) : "f"(v)); return r;
}
__device__ __forceinline__ float fsigmoid(float z) {
    return frcp(1.0f + __expf(-z));
}
__device__ __forceinline__ float4 ldg128(const float* p) {
    float4 v;
    asm("ld.global.nc.v4.f32 {%0, %1, %2, %3}, [%4];"
        : "=f"(v.x), "=f"(v.y), "=f"(v.z), "=f"(v.w) : "l"(p));
    return v;
}
__device__ __forceinline__ void st_stream_f2(float* p, float a, float b) {
    asm volatile("st.global.cs.v2.f32 [%0], {%1, %2};" :: "l"(p), "f"(a), "f"(b));
}

__global__ __launch_bounds__(NTH, 4)
void box_diamond_kernel(const float* __restrict__ x,
                        const float* __restrict__ t0,
                        const float* __restrict__ t1,
                        const float* __restrict__ t2,
                        float* __restrict__ out) {
    __shared__ __align__(16) float xs[2][32][PITCH];  // 36.9 KB, two tiles
    __shared__ float w1s[7][16];   // -W1 [d+3][p_local]
    __shared__ float w2s[8][16];   // 1-W2 [m][p_local]

    const int tid   = threadIdx.x;
    const int by    = blockIdx.y;           // p-tile of 16
    const int pbase = by * 16;
    const int b0    = blockIdx.x * 64;      // two consecutive 32-row tiles

    const int lane = tid & 31;
    const int w    = tid >> 5;

    // ---- t-parameter loads (registers; MUFU tables built from these) ----
    float rt0 = 0.f, rt1 = 0.f, rt2 = 0.f;
    const int pl_t = tid & 15;
    if (tid < 128) {
        rt0 = __ldg(t0 + pbase + pl_t);
        rt1 = __ldg(t1 + pbase + pl_t);
        rt2 = __ldg(t2 + pbase + pl_t);
    }

    // ---- LDG both tiles: lane holds the chunk destined for SMEM slot=lane.
    // slot s <-> (l = s>>2, g = s&3); gmem chunk c = g*8 + l = (s&3)*8+(s>>2).
    // The 32 lanes' addresses form one contiguous 512B row segment -> the
    // coalescer merges them into 4x128B regardless of lane order.
    const int c = (lane & 3) * 8 + (lane >> 2);
    const float* src = x + (size_t)b0 * D_TOT + (size_t)by * 128 + c * 4;

    float4 v0[4], v1[4];
    #pragma unroll
    for (int it = 0; it < 4; it++) {
        int r = it * 8 + w;                  // row 0..31 of tile 0
        v0[it] = ldg128(src + (size_t)r * D_TOT);
    }
    #pragma unroll
    for (int it = 0; it < 4; it++) {
        int r = it * 8 + w;
        v1[it] = ldg128(src + (size_t)(32 + r) * D_TOT);
    }

    // ---- build tables (pure MUFU; overlaps all loads in flight) ----
    if (tid < 112) {              // -W1: 7d x 16p
        int d  = tid >> 4;
        float dd = (float)(d - 3);
        w1s[d][pl_t] = -fsigmoid(dd * (rt2 - dd));
    }
    if (tid < 128) {              // 1-W2: 8m x 16p
        int m  = tid >> 4;
        float lf = (float)m;
        float z1 = (lf - rt0) * (rt1 - lf);
        float z2 = (7.0f - rt2 - lf) * lf;
        w2s[m][pl_t] = 1.0f - fsigmoid(z1) * fsigmoid(z2);
    }

    // ---- STS both tiles: linear slot = lane -> conflict-free STS.128 ----
    #pragma unroll
    for (int it = 0; it < 4; it++)
        *reinterpret_cast<float4*>(&xs[0][it * 8 + w][lane * 4]) = v0[it];
    #pragma unroll
    for (int it = 0; it < 4; it++)
        *reinterpret_cast<float4*>(&xs[1][it * 8 + w][lane * 4]) = v1[it];

    __syncthreads();               // the ONLY barrier

    // compute-side mapping: lane = b4*8 + sub
    const int b4   = lane >> 3;              // 0..3
    const int sub  = lane & 7;               // p-pair (p_local = 2*sub)
    const int row  = w * 4 + b4;             // 0..31 within tile
    const int roff = sub * 2;                // = g*4 + jp*2

    u64 w1r[7];
    #pragma unroll
    for (int d = 0; d < 7; d++)
        w1r[d] = *reinterpret_cast<const u64*>(&w1s[d][sub * 2]);

    const float LN2 = 0.6931471805599453f;

    #pragma unroll
    for (int t = 0; t < 2; t++) {
        // snapshot x: 8 conflict-free LDS.64
        // float offset of (l, g, jp) = (l*4+g)*4 + jp*2 = l*16 + g*4 + jp*2
        u64 nx[8];
        #pragma unroll
        for (int l = 0; l < 8; l++)
            nx[l] = *reinterpret_cast<const u64*>(&xs[t][row][l * 16 + roff]);

        // compute: 8 m, truncated l-window
        u64 num = ONE2, den = ONE2;
        #pragma unroll
        for (int m = 0; m < 8; m++) {
            const int lo = (m - 3 < 0) ? 0 : m - 3;
            const int hi = (m + 3 > 7) ? 7 : m + 3;
            u64 pr = fma2(nx[lo], w1r[lo - m + 3], ONE2);   // 1 - x*W1
            #pragma unroll
            for (int l = lo + 1; l <= hi; l++)
                pr = mul2(pr, fma2(nx[l], w1r[l - m + 3], ONE2));
            float a0, a1;
            unpack2(a0, a1, pr);
            u64 lg  = pack2(__log2f(a0), __log2f(a1));
            u64 w2v = *reinterpret_cast<const u64*>(&w2s[m][sub * 2]);
            num = mul2(num, fma2(lg, NEGLN2_2, w2v));   // s - W2
            den = mul2(den, fma2(lg, NEGLN2_2, ONE2));  // s
        }

        float n0, n1, d0, d1;
        unpack2(n0, n1, num);
        unpack2(d0, d1, den);
        float o0 = frcp(fmaf(-LN2, __log2f(n0) - __log2f(d0), 1.0f));
        float o1 = frcp(fmaf(-LN2, __log2f(n1) - __log2f(d1), 1.0f));

        // direct coalesced store (64B per b-row segment)
        int brow = b0 + t * 32 + row;
        st_stream_f2(out + (size_t)brow * P_TOT + pbase + sub * 2, o0, o1);
    }
}

extern "C" void kernel_launch(void* const* d_in, const int* in_sizes, int n_in,
                              void* d_out, int out_size) {
    const float* x  = (const float*)d_in[0];
    const float* t0 = (const float*)d_in[1];
    const float* t1 = (const float*)d_in[2];
    const float* t2 = (const float*)d_in[3];
    float* out = (float*)d_out;

    int B = in_sizes[0] / D_TOT;              // 4096
    dim3 grid(B / 64, P_TOT / 16);            // (64, 32) = 2048 blocks
    box_diamond_kernel<<<grid, NTH>>>(x, t0, t1, t2, out);
}

// round 12
// speedup vs baseline: 1.5000x; 1.2614x over previous
#include <cuda_runtime.h>
#include <cuda_bf16.h>

// Box_diamond: two-layer soft-AND over 8-wide bins.
// out[b,p] = 1/(1 - log prod_m( (s_m - W2[p,m]) / s_m )),
// s_m = 1 - log prod_{l:|l-m|<=3} (1 - x[..]*W1[p,l-m]),  p = 4g+j
// W1[p,d]=sigmoid(d*(t2-d)) <=6e-6 for |d|>=4 -> truncated window.
// R12: XOR-swizzled SMEM (chunk c=g*8+l stored at c'=g*8+(l^g)).
//  - LDG lanes linear  -> each 8-lane phase = one 128B line (no L1 ampl.)
//  - STS.128 phases    -> banks 0,4..28 (conflict-free)
//  - LDS.64 snapshot   -> 16 distinct wide banks per phase (PITCH=144)
// One barrier; direct coalesced stores; W1 in regs; f32x2 packed math.

#define D_TOT   4096
#define P_TOT   512
#define NTH     256
#define PITCH   144          // floats; 72 (8B words) mod 16 == 8

typedef unsigned long long u64;

#define ONE2     0x3F8000003F800000ULL  // {1.0f, 1.0f}
#define NEGLN2_2 0xBF317218BF317218ULL  // {-ln2, -ln2}

__device__ __forceinline__ u64 fma2(u64 a, u64 b, u64 c) {
    u64 d; asm("fma.rn.f32x2 %0, %1, %2, %3;" : "=l"(d) : "l"(a), "l"(b), "l"(c)); return d;
}
__device__ __forceinline__ u64 mul2(u64 a, u64 b) {
    u64 d; asm("mul.rn.f32x2 %0, %1, %2;" : "=l"(d) : "l"(a), "l"(b)); return d;
}
__device__ __forceinline__ u64 pack2(float lo, float hi) {
    u64 d; asm("mov.b64 %0, {%1, %2};" : "=l"(d) : "f"(lo), "f"(hi)); return d;
}
__device__ __forceinline__ void unpack2(float& lo, float& hi, u64 v) {
    asm("mov.b64 {%0, %1}, %2;" : "=f"(lo), "=f"(hi) : "l"(v));
}
__device__ __forceinline__ float frcp(float v) {
    float r; asm("rcp.approx.f32 %0, %1;" : "=f"(r) : "f"(v)); return r;
}
__device__ __forceinline__ float fsigmoid(float z) {
    return frcp(1.0f + __expf(-z));
}
__device__ __forceinline__ float4 ldg128(const float* p) {
    float4 v;
    asm("ld.global.nc.v4.f32 {%0, %1, %2, %3}, [%4];"
        : "=f"(v.x), "=f"(v.y), "=f"(v.z), "=f"(v.w) : "l"(p));
    return v;
}
__device__ __forceinline__ void st_stream_f2(float* p, float a, float b) {
    asm volatile("st.global.cs.v2.f32 [%0], {%1, %2};" :: "l"(p), "f"(a), "f"(b));
}

__global__ __launch_bounds__(NTH, 4)
void box_diamond_kernel(const float* __restrict__ x,
                        const float* __restrict__ t0,
                        const float* __restrict__ t1,
                        const float* __restrict__ t2,
                        float* __restrict__ out) {
    __shared__ __align__(16) float xs[2][32][PITCH];  // 36.9 KB, two tiles
    __shared__ float w1s[7][16];   // -W1 [d+3][p_local]
    __shared__ float w2s[8][16];   // 1-W2 [m][p_local]

    const int tid   = threadIdx.x;
    const int by    = blockIdx.y;           // p-tile of 16
    const int pbase = by * 16;
    const int b0    = blockIdx.x * 64;      // two consecutive 32-row tiles

    const int lane = tid & 31;
    const int w    = tid >> 5;

    // ---- t-parameter loads (registers; tables built from these) ----
    float rt0 = 0.f, rt1 = 0.f, rt2 = 0.f;
    const int pl_t = tid & 15;
    if (tid < 128) {
        rt0 = __ldg(t0 + pbase + pl_t);
        rt1 = __ldg(t1 + pbase + pl_t);
        rt2 = __ldg(t2 + pbase + pl_t);
    }

    // ---- LDG both tiles: lane = LINEAR chunk c -> perfectly merged phases.
    const float* src = x + (size_t)b0 * D_TOT + (size_t)by * 128 + lane * 4;

    float4 v0[4], v1[4];
    #pragma unroll
    for (int it = 0; it < 4; it++)
        v0[it] = ldg128(src + (size_t)(it * 8 + w) * D_TOT);
    #pragma unroll
    for (int it = 0; it < 4; it++)
        v1[it] = ldg128(src + (size_t)(32 + it * 8 + w) * D_TOT);

    // ---- build tables (pure MUFU; overlaps load flight) ----
    if (tid < 112) {              // -W1: 7d x 16p
        int d  = tid >> 4;
        float dd = (float)(d - 3);
        w1s[d][pl_t] = -fsigmoid(dd * (rt2 - dd));
    }
    if (tid < 128) {              // 1-W2: 8m x 16p
        int m  = tid >> 4;
        float lf = (float)m;
        float z1 = (lf - rt0) * (rt1 - lf);
        float z2 = (7.0f - rt2 - lf) * lf;
        w2s[m][pl_t] = 1.0f - fsigmoid(z1) * fsigmoid(z2);
    }

    // ---- STS both tiles at XOR-swizzled chunk c' = g*8 + (l^g) ----
    // g = lane>>3 (2 bits), l = lane&7 -> per 8-lane phase: banks 0,4..28.
    const int csw = (lane & 24) | ((lane ^ (lane >> 3)) & 7);
    #pragma unroll
    for (int it = 0; it < 4; it++)
        *reinterpret_cast<float4*>(&xs[0][it * 8 + w][csw * 4]) = v0[it];
    #pragma unroll
    for (int it = 0; it < 4; it++)
        *reinterpret_cast<float4*>(&xs[1][it * 8 + w][csw * 4]) = v1[it];

    __syncthreads();               // the ONLY barrier

    // compute-side mapping: lane = b4*8 + sub
    const int b4   = lane >> 3;              // 0..3
    const int sub  = lane & 7;               // p-pair (p_local = 2*sub)
    const int row  = w * 4 + b4;             // 0..31 within tile
    const int g    = sub >> 1;
    const int jp   = sub & 1;
    const int gbase = g * 32 + jp * 2;       // row-local float base

    u64 w1r[7];
    #pragma unroll
    for (int d = 0; d < 7; d++)
        w1r[d] = *reinterpret_cast<const u64*>(&w1s[d][sub * 2]);

    const float LN2 = 0.6931471805599453f;

    #pragma unroll
    for (int t = 0; t < 2; t++) {
        // snapshot x: 8 conflict-free LDS.64
        // float offset of (l, g, jp) = g*32 + ((l^g)<<2) + jp*2
        u64 nx[8];
        #pragma unroll
        for (int l = 0; l < 8; l++)
            nx[l] = *reinterpret_cast<const u64*>(
                &xs[t][row][gbase + ((l ^ g) << 2)]);

        // compute: 8 m, truncated l-window
        u64 num = ONE2, den = ONE2;
        #pragma unroll
        for (int m = 0; m < 8; m++) {
            const int lo = (m - 3 < 0) ? 0 : m - 3;
            const int hi = (m + 3 > 7) ? 7 : m + 3;
            u64 pr = fma2(nx[lo], w1r[lo - m + 3], ONE2);   // 1 - x*W1
            #pragma unroll
            for (int l = lo + 1; l <= hi; l++)
                pr = mul2(pr, fma2(nx[l], w1r[l - m + 3], ONE2));
            float a0, a1;
            unpack2(a0, a1, pr);
            u64 lg  = pack2(__log2f(a0), __log2f(a1));
            u64 w2v = *reinterpret_cast<const u64*>(&w2s[m][sub * 2]);
            num = mul2(num, fma2(lg, NEGLN2_2, w2v));   // s - W2
            den = mul2(den, fma2(lg, NEGLN2_2, ONE2));  // s
        }

        float n0, n1, d0, d1;
        unpack2(n0, n1, num);
        unpack2(d0, d1, den);
        float o0 = frcp(fmaf(-LN2, __log2f(n0) - __log2f(d0), 1.0f));
        float o1 = frcp(fmaf(-LN2, __log2f(n1) - __log2f(d1), 1.0f));

        // direct coalesced store (64B per b-row segment)
        int brow = b0 + t * 32 + row;
        st_stream_f2(out + (size_t)brow * P_TOT + pbase + sub * 2, o0, o1);
    }
}

extern "C" void kernel_launch(void* const* d_in, const int* in_sizes, int n_in,
                              void* d_out, int out_size) {
    const float* x  = (const float*)d_in[0];
    const float* t0 = (const float*)d_in[1];
    const float* t1 = (const float*)d_in[2];
    const float* t2 = (const float*)d_in[3];
    float* out = (float*)d_out;

    int B = in_sizes[0] / D_TOT;              // 4096
    dim3 grid(B / 64, P_TOT / 16);            // (64, 32) = 2048 blocks
    box_diamond_kernel<<<grid, NTH>>>(x, t0, t1, t2, out);
}